// round 16
// baseline (speedup 1.0000x reference)
#include <cuda_runtime.h>
#include <cstdint>

// LSHGaussian, fp16 mma.sync.m16n8k16 + ldmatrix (R13 inner loop), residency x2:
//   BM=64, TPB=256, grid=256 -> 2 CTAs/SM (32 warps/SM) and all 148 SMs used.
//   8 warps = 4 row-blocks x 2 j-halves; each warp 16 rows x 64 j (as R13).
//   U tile [j][ch] f16, row stride 144B (bank-disjoint ldmatrix);
//   scores via packed f32x2 chains; staging LDG->STS (no reg prefetch, the
//   co-resident CTA hides the gmem tail).
// out = P @ U - U,  P[i,j] = exp(-0.5*||ref_i-ref_j||^2).

#define N_PTS  16384
#define CCH    64
#define BM     64
#define BK     128
#define TPB    256
#define NTILES (N_PTS / BK)
#define USTRU  36          // u32 per j row (64 f16 + 8B pad) -> 144B
#define R2STR  12          // u64 per jp row in feature tile

#define US_BYTES (BK * USTRU * 4)      // 18432 per buffer
#define R2_BYTES (64 * R2STR * 8)      // 6144 per buffer
#define OFF_US0  0
#define OFF_US1  US_BYTES
#define OFF_R20  (2 * US_BYTES)
#define OFF_R21  (2 * US_BYTES + R2_BYTES)
#define SMEM_TOTAL (2 * US_BYTES + 2 * R2_BYTES)   // 49152

typedef unsigned long long u64;

__device__ __forceinline__ float ex2f(float x) {
    float r; asm("ex2.approx.ftz.f32 %0, %1;" : "=f"(r) : "f"(x)); return r;
}
__device__ __forceinline__ uint32_t smem_u32(const void* p) {
    uint32_t a;
    asm("{ .reg .u64 t; cvta.to.shared.u64 t, %1; cvt.u32.u64 %0, t; }" : "=r"(a) : "l"(p));
    return a;
}
#define FMA2(acc, a, b) asm("fma.rn.f32x2 %0, %1, %2, %0;" : "+l"(acc) : "l"(a), "l"(b))
#define ADD2(d, a, b)   asm("add.rn.f32x2 %0, %1, %2;" : "=l"(d) : "l"(a), "l"(b))
#define PACKB(d, f)     asm("mov.b64 %0, {%1, %1};" : "=l"(d) : "f"(f))
#define PACK2(d, lo, hi) asm("mov.b64 %0, {%1, %2};" : "=l"(d) : "f"(lo), "f"(hi))
#define UNPK(lo, hi, v) asm("mov.b64 {%0, %1}, %2;" : "=f"(lo), "=f"(hi) : "l"(v))
#define CVTH(d, hi, lo) asm("cvt.rn.f16x2.f32 %0, %1, %2;" : "=r"(d) : "f"(hi), "f"(lo))
#define LDSM4T(r0, r1, r2, r3, addr) \
    asm volatile("ldmatrix.sync.aligned.m8n8.x4.trans.shared.b16 {%0,%1,%2,%3}, [%4];" \
                 : "=r"(r0), "=r"(r1), "=r"(r2), "=r"(r3) : "r"(addr))
#define MMA16(cc, a0, a1, a2, a3, b0, b1) \
    asm volatile("mma.sync.aligned.m16n8k16.row.col.f32.f16.f16.f32 " \
                 "{%0,%1,%2,%3}, {%4,%5,%6,%7}, {%8,%9}, {%0,%1,%2,%3};" \
                 : "+f"((cc)[0]), "+f"((cc)[1]), "+f"((cc)[2]), "+f"((cc)[3]) \
                 : "r"(a0), "r"(a1), "r"(a2), "r"(a3), "r"(b0), "r"(b1))

__global__ void __launch_bounds__(TPB, 2)
lsh_res2_kernel(const float* __restrict__ U, const float* __restrict__ ref,
                float* __restrict__ out)
{
    extern __shared__ __align__(16) char smem[];
    uint32_t* const UsB[2] = { (uint32_t*)(smem + OFF_US0), (uint32_t*)(smem + OFF_US1) };
    u64*      const R2B[2] = { (u64*)(smem + OFF_R20), (u64*)(smem + OFF_R21) };
    const uint32_t su = smem_u32(smem);

    const int tid  = threadIdx.x;
    const int wid  = tid >> 5;
    const int lane = tid & 31;
    const int g    = lane >> 2;        // 0..7
    const int kin  = lane & 3;         // 0..3
    const int h    = wid >> 2;         // j-half (0/1)
    const int wm   = wid & 3;          // row-block (16 rows)
    const float L2E = 1.4426950408889634f;
    const int rbase = blockIdx.x * BM + wm * 16;

    // per-lane ldmatrix base: matrix i = lane>>3, row r = lane&7
    const int jpart  = ((lane >> 3) & 1) * 8 + (lane & 7);
    const int chpart = lane >> 4;
    const uint32_t Lbase = (uint32_t)((h * 64 + jpart) * 144 + chpart * 16);

    // 2 A-rows per thread (g, g+8): packed-broadcast ri (scaled) + bias.
    u64 ri2[2][5], bi2[2];
    #pragma unroll
    for (int rr = 0; rr < 2; ++rr) {
        const float* rp = ref + (size_t)(rbase + rr * 8 + g) * 5;
        float s = 0.f;
        #pragma unroll
        for (int k = 0; k < 5; ++k) {
            float v = rp[k];
            s = fmaf(v, v, s);
            PACKB(ri2[rr][k], v * L2E);
        }
        PACKB(bi2[rr], -0.5f * L2E * s);
    }

    float c[8][4];
    #pragma unroll
    for (int nt = 0; nt < 8; ++nt)
        #pragma unroll
        for (int q = 0; q < 4; ++q) c[nt][q] = 0.f;

    // ── stage tile 0 ──
    {
        const float4* Ug = (const float4*)U;
        #pragma unroll
        for (int it = 0; it < 8; ++it) {
            int f = it * TPB + tid;            // 0..2047
            int j = f >> 4, c4 = f & 15;
            float4 v = Ug[f];
            uint2 w;
            CVTH(w.x, v.y, v.x);
            CVTH(w.y, v.w, v.z);
            *(uint2*)&UsB[0][j * USTRU + c4 * 2] = w;
        }
        if (tid < 64) {
            const float* ra = ref + (size_t)(2 * tid) * 5;
            const float* rb = ra + 5;
            float sa = 0.f, sb = 0.f;
            u64* R = &R2B[0][tid * R2STR];
            #pragma unroll
            for (int k = 0; k < 5; ++k) {
                float a = ra[k], b = rb[k];
                sa = fmaf(a, a, sa); sb = fmaf(b, b, sb);
                PACK2(R[k], a, b);
            }
            PACK2(R[5], -0.5f * L2E * sa, -0.5f * L2E * sb);
        }
    }
    __syncthreads();

    for (int t = 0; t < NTILES; ++t) {
        const int buf = t & 1, nbuf = buf ^ 1;

        // ── compute tile t: 4 k-chunks of 16 j ──
        {
            const u64* __restrict__ R2 = R2B[buf];
            const uint32_t Ls = su + (buf ? OFF_US1 : OFF_US0) + Lbase;
            #pragma unroll
            for (int kc = 0; kc < 4; ++kc) {
                const int jpA = h * 32 + kc * 8 + kin;
                const int jpB = jpA + 4;
                const u64* Ra = &R2[jpA * R2STR];
                const u64* Rb = &R2[jpB * R2STR];
                ulonglong2 xa01 = *(const ulonglong2*)&Ra[0];
                ulonglong2 xa23 = *(const ulonglong2*)&Ra[2];
                ulonglong2 xa45 = *(const ulonglong2*)&Ra[4];
                ulonglong2 xb01 = *(const ulonglong2*)&Rb[0];
                ulonglong2 xb23 = *(const ulonglong2*)&Rb[2];
                ulonglong2 xb45 = *(const ulonglong2*)&Rb[4];

                u64 tA0, tA1, tB0, tB1;
                ADD2(tA0, xa45.y, bi2[0]); ADD2(tA1, xa45.y, bi2[1]);
                ADD2(tB0, xb45.y, bi2[0]); ADD2(tB1, xb45.y, bi2[1]);
                FMA2(tA0, ri2[0][0], xa01.x); FMA2(tA1, ri2[1][0], xa01.x);
                FMA2(tB0, ri2[0][0], xb01.x); FMA2(tB1, ri2[1][0], xb01.x);
                FMA2(tA0, ri2[0][1], xa01.y); FMA2(tA1, ri2[1][1], xa01.y);
                FMA2(tB0, ri2[0][1], xb01.y); FMA2(tB1, ri2[1][1], xb01.y);
                FMA2(tA0, ri2[0][2], xa23.x); FMA2(tA1, ri2[1][2], xa23.x);
                FMA2(tB0, ri2[0][2], xb23.x); FMA2(tB1, ri2[1][2], xb23.x);
                FMA2(tA0, ri2[0][3], xa23.y); FMA2(tA1, ri2[1][3], xa23.y);
                FMA2(tB0, ri2[0][3], xb23.y); FMA2(tB1, ri2[1][3], xb23.y);
                FMA2(tA0, ri2[0][4], xa45.x); FMA2(tA1, ri2[1][4], xa45.x);
                FMA2(tB0, ri2[0][4], xb45.x); FMA2(tB1, ri2[1][4], xb45.x);

                float e, o;
                uint32_t a0, a1, a2, a3;
                UNPK(e, o, tA0); e = ex2f(e); o = ex2f(o); CVTH(a0, o, e);
                UNPK(e, o, tA1); e = ex2f(e); o = ex2f(o); CVTH(a1, o, e);
                UNPK(e, o, tB0); e = ex2f(e); o = ex2f(o); CVTH(a2, o, e);
                UNPK(e, o, tB1); e = ex2f(e); o = ex2f(o); CVTH(a3, o, e);

                const uint32_t ad = Ls + (uint32_t)(kc * 16 * 144);
                #pragma unroll
                for (int q = 0; q < 4; ++q) {
                    uint32_t b00, b01, b10, b11;
                    LDSM4T(b00, b01, b10, b11, ad + (uint32_t)(q * 32));
                    MMA16(c[2 * q],     a0, a1, a2, a3, b00, b01);
                    MMA16(c[2 * q + 1], a0, a1, a2, a3, b10, b11);
                }
            }
        }

        // ── stage tile t+1 into nbuf (LDG here; co-resident CTA hides latency) ──
        if (t + 1 < NTILES) {
            const float4* Ug = (const float4*)(U + (size_t)(t + 1) * BK * CCH);
            uint32_t* Ud = UsB[nbuf];
            #pragma unroll
            for (int it = 0; it < 8; ++it) {
                int f = it * TPB + tid, j = f >> 4, c4 = f & 15;
                float4 v = Ug[f];
                uint2 w;
                CVTH(w.x, v.y, v.x);
                CVTH(w.y, v.w, v.z);
                *(uint2*)&Ud[j * USTRU + c4 * 2] = w;
            }
            if (tid < 64) {
                const float* ra = ref + (size_t)((t + 1) * BK + 2 * tid) * 5;
                float sa = 0.f, sb = 0.f;
                float pa[5], pb[5];
                #pragma unroll
                for (int k = 0; k < 5; ++k) { pa[k] = ra[k]; pb[k] = ra[k + 5]; }
                u64* R = &R2B[nbuf][tid * R2STR];
                #pragma unroll
                for (int k = 0; k < 5; ++k) {
                    sa = fmaf(pa[k], pa[k], sa); sb = fmaf(pb[k], pb[k], sb);
                    PACK2(R[k], pa[k], pb[k]);
                }
                PACK2(R[5], -0.5f * L2E * sa, -0.5f * L2E * sb);
            }
        }
        __syncthreads();
    }

    // ── reduce j-halves (h=1 -> h=0) via smem, then out = C - U ──
    float4* Sred = (float4*)smem;   // 4 wm x 8 nt x 32 lanes x float4 = 16 KB
    if (h == 1) {
        #pragma unroll
        for (int nt = 0; nt < 8; ++nt)
            Sred[(wm * 8 + nt) * 32 + lane] = make_float4(c[nt][0], c[nt][1],
                                                          c[nt][2], c[nt][3]);
    }
    __syncthreads();
    if (h == 0) {
        const int rl = rbase + g, rh = rl + 8;
        const int n0 = 2 * kin;
        #pragma unroll
        for (int nt = 0; nt < 8; ++nt) {
            float4 v = Sred[(wm * 8 + nt) * 32 + lane];
            const int col = nt * 8 + n0;
            float2 ul = *(const float2*)(U + (size_t)rl * CCH + col);
            float2 uh = *(const float2*)(U + (size_t)rh * CCH + col);
            float2 ol, oh;
            ol.x = (c[nt][0] + v.x) - ul.x; ol.y = (c[nt][1] + v.y) - ul.y;
            oh.x = (c[nt][2] + v.z) - uh.x; oh.y = (c[nt][3] + v.w) - uh.y;
            *(float2*)(out + (size_t)rl * CCH + col) = ol;
            *(float2*)(out + (size_t)rh * CCH + col) = oh;
        }
    }
}

extern "C" void kernel_launch(void* const* d_in, const int* in_sizes, int n_in,
                              void* d_out, int out_size)
{
    const float* U   = (const float*)d_in[0];   // [N, 64]
    const float* ref = (const float*)d_in[1];   // [N, 5]
    float* out = (float*)d_out;                 // [N, 64]
    (void)in_sizes; (void)n_in; (void)out_size;

    cudaFuncSetAttribute(lsh_res2_kernel,
                         cudaFuncAttributeMaxDynamicSharedMemorySize, SMEM_TOTAL);
    lsh_res2_kernel<<<N_PTS / BM, TPB, SMEM_TOTAL>>>(U, ref, out);
}